// round 10
// baseline (speedup 1.0000x reference)
#include <cuda_runtime.h>
#include <cuda_bf16.h>
#include <cstdint>

// ---------------- problem constants ----------------
#define S_    64
#define B_    1024
#define D_    512
#define H_    8
#define DH_   64
#define NL_   4
#define DFF_  2048
#define NT    (S_ * B_)          // 65536 tokens
#define BD    (B_ * D_)          // 524288
#define KBITS 32

// ---------------- scratch (no cudaMalloc allowed) ----------------
__device__ float g_x[NT * D_];                                   // residual (fp32)
__device__ float g_qkv[NT * 3 * D_];                             // qkv (fp32)
__device__ float g_pool[B_ * D_];
__device__ __nv_bfloat16 g_ahi[NT * D_];                         // activation bf16 hi
__device__ uint8_t g_a8h[NT * D_];                               // activation e4m3(x*2^4)
__device__ uint8_t g_a8l[NT * D_];                               // activation e4m3(lo*2^13)
__device__ __nv_bfloat16 g_hhi[(size_t)NT * DFF_];               // hidden bf16 hi
__device__ uint8_t g_h8h[(size_t)NT * DFF_];
__device__ uint8_t g_h8l[(size_t)NT * DFF_];
__device__ __nv_bfloat16 g_whi[DFF_ * D_];                       // weight bf16(w)*2^24
__device__ uint8_t g_w8h[DFF_ * D_];                             // e4m3(w*2^11)
__device__ uint8_t g_w8l[DFF_ * D_];                             // e4m3(wlo*2^20)

// scales
#define DESCALE (1.0f / 16777216.0f)     // 2^-24
#define SAH 16.0f                        // 2^4
#define SAL 8192.0f                      // 2^13
#define SWH 2048.0f                      // 2^11
#define SWL 1048576.0f                   // 2^20
#define WBF_SCALE 16777216.0f            // 2^24 (exact on bf16)

// ---------------- helpers ----------------
__device__ __forceinline__ uint32_t smem_u32(const void* p) {
    uint32_t a;
    asm("{ .reg .u64 t; cvta.to.shared.u64 t, %1; cvt.u32.u64 %0, t; }" : "=r"(a) : "l"(p));
    return a;
}
__device__ __forceinline__ uint32_t packbf(float a, float b) {
    __nv_bfloat16 ha = __float2bfloat16(a), hb = __float2bfloat16(b);
    return (uint32_t)__bfloat16_as_ushort(ha) | ((uint32_t)__bfloat16_as_ushort(hb) << 16);
}
__device__ __forceinline__ uint16_t pack_e4m3_2(float f0, float f1) {
    uint16_t r;
    asm("cvt.rn.satfinite.e4m3x2.f32 %0, %1, %2;" : "=h"(r) : "f"(f1), "f"(f0));
    return r;   // byte0 = f0, byte1 = f1
}
__device__ __forceinline__ uint32_t pack_e4m3_4(float f0, float f1, float f2, float f3) {
    return (uint32_t)pack_e4m3_2(f0, f1) | ((uint32_t)pack_e4m3_2(f2, f3) << 16);
}

#define CP16(dst, src) \
    asm volatile("cp.async.ca.shared.global [%0], [%1], 16;" :: "r"(dst), "l"(src) : "memory")
#define CPCOMMIT() asm volatile("cp.async.commit_group;" ::: "memory")
#define CPWAIT(n)  asm volatile("cp.async.wait_group %0;" :: "n"(n) : "memory")

__device__ __forceinline__ void ldsm4(uint32_t* r, uint32_t addr) {
    asm volatile("ldmatrix.sync.aligned.m8n8.x4.shared.b16 {%0,%1,%2,%3}, [%4];"
                 : "=r"(r[0]), "=r"(r[1]), "=r"(r[2]), "=r"(r[3]) : "r"(addr));
}
__device__ __forceinline__ void mma16816(float* d, const uint32_t* a, const uint32_t* b) {
    asm volatile("mma.sync.aligned.m16n8k16.row.col.f32.bf16.bf16.f32 "
                 "{%0,%1,%2,%3}, {%4,%5,%6,%7}, {%8,%9}, {%0,%1,%2,%3};"
                 : "+f"(d[0]), "+f"(d[1]), "+f"(d[2]), "+f"(d[3])
                 : "r"(a[0]), "r"(a[1]), "r"(a[2]), "r"(a[3]), "r"(b[0]), "r"(b[1]));
}
__device__ __forceinline__ void mma16832f8(float* d, const uint32_t* a, const uint32_t* b) {
    asm volatile("mma.sync.aligned.m16n8k32.row.col.f32.e4m3.e4m3.f32 "
                 "{%0,%1,%2,%3}, {%4,%5,%6,%7}, {%8,%9}, {%0,%1,%2,%3};"
                 : "+f"(d[0]), "+f"(d[1]), "+f"(d[2]), "+f"(d[3])
                 : "r"(a[0]), "r"(a[1]), "r"(a[2]), "r"(a[3]), "r"(b[0]), "r"(b[1]));
}

__device__ __forceinline__ float qgelu(float t) { return t / (1.0f + __expf(-1.702f * t)); }

// smem stage (64KB): Abf16(16K) Wbf16(16K) A8packed(16K) W8packed(16K); 2 stages = 128KB
#define OFF_WBF  16384
#define OFF_A8   32768
#define OFF_W8   49152
#define STG_SZ   65536
#define GEMM_SMEM (2 * STG_SZ)

// ---------------- MMA GEMM: C[n,m] = epi(sum_k A[n,k]*W[m,k] + bias[m]) ----------------
// CTA tile: 128 tokens x 128 outputs, KC=64, 8 warps (warp tile 64 tok x 32 out).
// Pass 1 in bf16 (W pre-scaled 2^24); passes 2+3 in fp8 e4m3 k32 — single accumulator.
// EPI: 0 = f32 +bias ; 1 = f32 +bias+res ; 2 = QuickGELU -> (bf16 hi, fp8 hi, fp8 lo)
template <int EPI>
__global__ __launch_bounds__(256, 1) void mma_gemm(
    const __nv_bfloat16* __restrict__ Ahi, const uint8_t* __restrict__ A8h,
    const uint8_t* __restrict__ A8l,
    const __nv_bfloat16* __restrict__ Whi, const uint8_t* __restrict__ W8h,
    const uint8_t* __restrict__ W8l,
    const float* __restrict__ bias, const float* __restrict__ res,
    float* __restrict__ C, __nv_bfloat16* __restrict__ Chi,
    uint8_t* __restrict__ C8h, uint8_t* __restrict__ C8l,
    int M, int K)
{
    extern __shared__ __align__(128) char smem[];
    const uint32_t sb = smem_u32(smem);
    const int tid = threadIdx.x;
    const int lane = tid & 31;
    const int wid = tid >> 5;
    const int m0 = blockIdx.x * 128;
    const int n0 = blockIdx.y * 128;
    const int wm = (wid & 1) * 64;
    const int wn = (wid >> 1) * 32;
    const int NCH = K >> 6;
    const int lcc = tid & 7;

    float acc[4][4][4];
    #pragma unroll
    for (int a = 0; a < 4; a++)
        #pragma unroll
        for (int b = 0; b < 4; b++)
            #pragma unroll
            for (int c = 0; c < 4; c++) acc[a][b][c] = 0.0f;

    // ---- stage loader ----
    auto load_stage = [&](int c, int s) {
        const uint32_t stb = sb + s * STG_SZ;
        #pragma unroll
        for (int j = 0; j < 4; j++) {
            const int r = (j * 256 + tid) >> 3;
            const uint32_t dst = (uint32_t)(r * 128 + ((lcc ^ (r & 7)) << 4));
            const size_t arow = (size_t)(n0 + r) * K + c * 64;
            const size_t wrow = (size_t)(m0 + r) * K + c * 64;
            // bf16 tiles (8 chunks of 8 bf16)
            CP16(stb + dst,           Ahi + arow + lcc * 8);
            CP16(stb + OFF_WBF + dst, Whi + wrow + lcc * 8);
            // fp8 packed tiles: chunks 0-3 = hi (16 fp8 each), 4-7 = lo
            const uint8_t* a8src = (lcc < 4) ? (A8h + arow + lcc * 16)
                                             : (A8l + arow + (lcc - 4) * 16);
            const uint8_t* w8src = (lcc < 4) ? (W8h + wrow + lcc * 16)
                                             : (W8l + wrow + (lcc - 4) * 16);
            CP16(stb + OFF_A8 + dst, a8src);
            CP16(stb + OFF_W8 + dst, w8src);
        }
        CPCOMMIT();
    };

    load_stage(0, 0);

    const int g  = lane >> 3;
    const int lr = lane & 7;

    for (int c = 0; c < NCH; c++) {
        if (c + 1 < NCH) { load_stage(c + 1, (c + 1) & 1); CPWAIT(1); }
        else             { CPWAIT(0); }
        __syncthreads();

        const uint32_t stb = sb + (c & 1) * STG_SZ;

        // ---- bf16 main pass: 4 x k16 ----
        #pragma unroll
        for (int ks = 0; ks < 4; ks++) {
            uint32_t af[4][4], bf[2][4];
            #pragma unroll
            for (int mi = 0; mi < 4; mi++) {
                const int row = wm + mi * 16 + ((g & 1) << 3) + lr;
                const int ch = ks * 2 + (g >> 1);
                ldsm4(af[mi], stb + row * 128 + ((ch ^ (row & 7)) << 4));
            }
            #pragma unroll
            for (int np = 0; np < 2; np++) {
                const int row = wn + np * 16 + ((g >> 1) << 3) + lr;
                const int ch = ks * 2 + (g & 1);
                ldsm4(bf[np], stb + OFF_WBF + row * 128 + ((ch ^ (row & 7)) << 4));
            }
            #pragma unroll
            for (int mi = 0; mi < 4; mi++)
                #pragma unroll
                for (int nt = 0; nt < 4; nt++)
                    mma16816(acc[mi][nt], af[mi], &bf[nt >> 1][(nt & 1) * 2]);
        }

        // ---- fp8 correction passes: 2 x k32 ----
        #pragma unroll
        for (int s = 0; s < 2; s++) {
            uint32_t a8h[4][4], a8l[4][4], w8h[2][4], w8l[2][4];
            #pragma unroll
            for (int mi = 0; mi < 4; mi++) {
                const int row = wm + mi * 16 + ((g & 1) << 3) + lr;
                const int ch = s * 2 + (g >> 1);
                ldsm4(a8h[mi], stb + OFF_A8 + row * 128 + ((ch       ^ (row & 7)) << 4));
                ldsm4(a8l[mi], stb + OFF_A8 + row * 128 + (((ch + 4) ^ (row & 7)) << 4));
            }
            #pragma unroll
            for (int np = 0; np < 2; np++) {
                const int row = wn + np * 16 + ((g >> 1) << 3) + lr;
                const int ch = s * 2 + (g & 1);
                ldsm4(w8h[np], stb + OFF_W8 + row * 128 + ((ch       ^ (row & 7)) << 4));
                ldsm4(w8l[np], stb + OFF_W8 + row * 128 + (((ch + 4) ^ (row & 7)) << 4));
            }
            // pass 2: Alo(fp8) * Whi(fp8)  -> scale 2^13 * 2^11 = 2^24
            #pragma unroll
            for (int mi = 0; mi < 4; mi++)
                #pragma unroll
                for (int nt = 0; nt < 4; nt++)
                    mma16832f8(acc[mi][nt], a8l[mi], &w8h[nt >> 1][(nt & 1) * 2]);
            // pass 3: Ahi(fp8) * Wlo(fp8)  -> scale 2^4 * 2^20 = 2^24
            #pragma unroll
            for (int mi = 0; mi < 4; mi++)
                #pragma unroll
                for (int nt = 0; nt < 4; nt++)
                    mma16832f8(acc[mi][nt], a8h[mi], &w8l[nt >> 1][(nt & 1) * 2]);
        }
        __syncthreads();
    }

    // ---- epilogue (descale 2^-24) ----
    const int r4 = lane >> 2;
    const int c2 = (lane & 3) * 2;
    #pragma unroll
    for (int mi = 0; mi < 4; mi++) {
        #pragma unroll
        for (int nt = 0; nt < 4; nt++) {
            const int row = n0 + wm + mi * 16 + r4;
            const int col = m0 + wn + nt * 8 + c2;
            const float b0 = bias[col], b1 = bias[col + 1];
            float v0 = acc[mi][nt][0] * DESCALE + b0, v1 = acc[mi][nt][1] * DESCALE + b1;
            float v2 = acc[mi][nt][2] * DESCALE + b0, v3 = acc[mi][nt][3] * DESCALE + b1;
            const size_t o0 = (size_t)row * M + col;
            const size_t o1 = (size_t)(row + 8) * M + col;
            if (EPI == 1) {
                const float2 r0 = *(const float2*)&res[o0];
                const float2 r1 = *(const float2*)&res[o1];
                v0 += r0.x; v1 += r0.y; v2 += r1.x; v3 += r1.y;
            }
            if (EPI == 2) {
                v0 = qgelu(v0); v1 = qgelu(v1); v2 = qgelu(v2); v3 = qgelu(v3);
                const __nv_bfloat16 h0 = __float2bfloat16(v0), h1 = __float2bfloat16(v1);
                const __nv_bfloat16 h2 = __float2bfloat16(v2), h3 = __float2bfloat16(v3);
                *(uint32_t*)&Chi[o0] = (uint32_t)__bfloat16_as_ushort(h0)
                                     | ((uint32_t)__bfloat16_as_ushort(h1) << 16);
                *(uint32_t*)&Chi[o1] = (uint32_t)__bfloat16_as_ushort(h2)
                                     | ((uint32_t)__bfloat16_as_ushort(h3) << 16);
                *(uint16_t*)&C8h[o0] = pack_e4m3_2(v0 * SAH, v1 * SAH);
                *(uint16_t*)&C8h[o1] = pack_e4m3_2(v2 * SAH, v3 * SAH);
                *(uint16_t*)&C8l[o0] = pack_e4m3_2((v0 - __bfloat162float(h0)) * SAL,
                                                   (v1 - __bfloat162float(h1)) * SAL);
                *(uint16_t*)&C8l[o1] = pack_e4m3_2((v2 - __bfloat162float(h2)) * SAL,
                                                   (v3 - __bfloat162float(h3)) * SAL);
            } else {
                *(float2*)&C[o0] = make_float2(v0, v1);
                *(float2*)&C[o1] = make_float2(v2, v3);
            }
        }
    }
}

// ---------------- weight convert: fp32 -> (bf16*2^24, fp8 hi, fp8 lo) ----------------
__global__ void wconv_kernel(const float* __restrict__ w,
                             __nv_bfloat16* __restrict__ whi,
                             uint8_t* __restrict__ w8h, uint8_t* __restrict__ w8l) {
    const int i = blockIdx.x * blockDim.x + threadIdx.x;
    const float4 v = *(const float4*)&w[i * 4];
    const __nv_bfloat16 h0 = __float2bfloat16(v.x), h1 = __float2bfloat16(v.y);
    const __nv_bfloat16 h2 = __float2bfloat16(v.z), h3 = __float2bfloat16(v.w);
    uint2 hb;
    hb.x = packbf(__bfloat162float(h0) * WBF_SCALE, __bfloat162float(h1) * WBF_SCALE);
    hb.y = packbf(__bfloat162float(h2) * WBF_SCALE, __bfloat162float(h3) * WBF_SCALE);
    *(uint2*)&whi[i * 4] = hb;
    *(uint32_t*)&w8h[i * 4] = pack_e4m3_4(v.x * SWH, v.y * SWH, v.z * SWH, v.w * SWH);
    *(uint32_t*)&w8l[i * 4] = pack_e4m3_4((v.x - __bfloat162float(h0)) * SWL,
                                          (v.y - __bfloat162float(h1)) * SWL,
                                          (v.z - __bfloat162float(h2)) * SWL,
                                          (v.w - __bfloat162float(h3)) * SWL);
}

// ---------------- positional encoding add ----------------
__global__ void pe_add_kernel(const float* __restrict__ xin, float* __restrict__ xout) {
    int idx = blockIdx.x * blockDim.x + threadIdx.x;
    int d = idx & (D_ - 1);
    int s = idx >> 19;
    int j2 = d & ~1;
    float ang = (float)s * expf((float)j2 * (-9.210340371976184f / 512.0f));
    float pe = ((d & 1) ? cosf(ang) : sinf(ang)) * 0.04419417382415922f;
    xout[idx] = xin[idx] + pe;
}

// ---------------- layernorm -> (bf16 hi, fp8 hi, fp8 lo) ----------------
__global__ void ln_kernel(const float* __restrict__ x,
                          __nv_bfloat16* __restrict__ yhi,
                          uint8_t* __restrict__ y8h, uint8_t* __restrict__ y8l,
                          const float* __restrict__ g, const float* __restrict__ b) {
    const int row = blockIdx.x;
    const int t = threadIdx.x;
    const size_t base = (size_t)row * D_ + t * 4;
    const float4 v = *(const float4*)&x[base];
    float s = v.x + v.y + v.z + v.w;
    float q = v.x * v.x + v.y * v.y + v.z * v.z + v.w * v.w;
    #pragma unroll
    for (int m = 16; m > 0; m >>= 1) {
        s += __shfl_xor_sync(0xffffffffu, s, m);
        q += __shfl_xor_sync(0xffffffffu, q, m);
    }
    __shared__ float ss[4], qq[4];
    if ((t & 31) == 0) { ss[t >> 5] = s; qq[t >> 5] = q; }
    __syncthreads();
    s = ss[0] + ss[1] + ss[2] + ss[3];
    q = qq[0] + qq[1] + qq[2] + qq[3];
    const float mean = s * (1.0f / 512.0f);
    const float var  = q * (1.0f / 512.0f) - mean * mean;
    const float rstd = rsqrtf(var + 1e-5f);
    const float4 gg = *(const float4*)&g[t * 4];
    const float4 bb = *(const float4*)&b[t * 4];
    const float o0 = (v.x - mean) * rstd * gg.x + bb.x;
    const float o1 = (v.y - mean) * rstd * gg.y + bb.y;
    const float o2 = (v.z - mean) * rstd * gg.z + bb.z;
    const float o3 = (v.w - mean) * rstd * gg.w + bb.w;
    const __nv_bfloat16 h0 = __float2bfloat16(o0), h1 = __float2bfloat16(o1);
    const __nv_bfloat16 h2 = __float2bfloat16(o2), h3 = __float2bfloat16(o3);
    uint2 hb;
    hb.x = (uint32_t)__bfloat16_as_ushort(h0) | ((uint32_t)__bfloat16_as_ushort(h1) << 16);
    hb.y = (uint32_t)__bfloat16_as_ushort(h2) | ((uint32_t)__bfloat16_as_ushort(h3) << 16);
    *(uint2*)&yhi[base] = hb;
    *(uint32_t*)&y8h[base] = pack_e4m3_4(o0 * SAH, o1 * SAH, o2 * SAH, o3 * SAH);
    *(uint32_t*)&y8l[base] = pack_e4m3_4((o0 - __bfloat162float(h0)) * SAL,
                                         (o1 - __bfloat162float(h1)) * SAL,
                                         (o2 - __bfloat162float(h2)) * SAL,
                                         (o3 - __bfloat162float(h3)) * SAL);
}

// ---------------- attention: one CTA per (batch, head) ----------------
__global__ __launch_bounds__(256) void attn_kernel(const float* __restrict__ qkv,
                                                   __nv_bfloat16* __restrict__ ohi,
                                                   uint8_t* __restrict__ o8h,
                                                   uint8_t* __restrict__ o8l) {
    __shared__ __align__(16) float qs[64 * 64];
    __shared__ __align__(16) float kst[64 * 64];
    __shared__ __align__(16) float vs[64 * 64];

    const int b = blockIdx.x;
    const int h = blockIdx.y;
    const int tid = threadIdx.x;
    const float* base = qkv + (size_t)b * (3 * D_) + h * DH_;

    #pragma unroll
    for (int it = 0; it < 4; it++) {
        const int idx = tid + it * 256;
        const int s = idx >> 4;
        const int f = idx & 15;
        const size_t g = (size_t)s * (B_ * 3 * D_) + f * 4;
        const float4 qv = *(const float4*)(base + g);
        const float4 kv = *(const float4*)(base + 512 + g);
        const float4 vv = *(const float4*)(base + 1024 + g);
        *(float4*)&qs[s * 64 + f * 4] = qv;
        kst[(f * 4 + 0) * 64 + s] = kv.x;
        kst[(f * 4 + 1) * 64 + s] = kv.y;
        kst[(f * 4 + 2) * 64 + s] = kv.z;
        kst[(f * 4 + 3) * 64 + s] = kv.w;
        *(float4*)&vs[s * 64 + f * 4] = vv;
    }
    __syncthreads();

    const int tx = tid & 15;
    const int ty = tid >> 4;

    float sc[4][4] = {};
    for (int d0 = 0; d0 < 64; d0 += 4) {
        const float4 k0 = *(const float4*)&kst[(d0 + 0) * 64 + tx * 4];
        const float4 k1 = *(const float4*)&kst[(d0 + 1) * 64 + tx * 4];
        const float4 k2 = *(const float4*)&kst[(d0 + 2) * 64 + tx * 4];
        const float4 k3 = *(const float4*)&kst[(d0 + 3) * 64 + tx * 4];
        #pragma unroll
        for (int i = 0; i < 4; i++) {
            const float4 q = *(const float4*)&qs[(ty * 4 + i) * 64 + d0];
            sc[i][0] += q.x * k0.x + q.y * k1.x + q.z * k2.x + q.w * k3.x;
            sc[i][1] += q.x * k0.y + q.y * k1.y + q.z * k2.y + q.w * k3.y;
            sc[i][2] += q.x * k0.z + q.y * k1.z + q.z * k2.z + q.w * k3.z;
            sc[i][3] += q.x * k0.w + q.y * k1.w + q.z * k2.w + q.w * k3.w;
        }
    }

    float p[4][4];
    #pragma unroll
    for (int i = 0; i < 4; i++) {
        #pragma unroll
        for (int j = 0; j < 4; j++) sc[i][j] *= 0.125f;
        float m = fmaxf(fmaxf(sc[i][0], sc[i][1]), fmaxf(sc[i][2], sc[i][3]));
        #pragma unroll
        for (int msk = 1; msk < 16; msk <<= 1) m = fmaxf(m, __shfl_xor_sync(0xffffffffu, m, msk));
        float s = 0.0f;
        #pragma unroll
        for (int j = 0; j < 4; j++) { p[i][j] = __expf(sc[i][j] - m); s += p[i][j]; }
        #pragma unroll
        for (int msk = 1; msk < 16; msk <<= 1) s += __shfl_xor_sync(0xffffffffu, s, msk);
        const float inv = 1.0f / s;
        #pragma unroll
        for (int j = 0; j < 4; j++) p[i][j] *= inv;
    }

    __syncthreads();
    #pragma unroll
    for (int i = 0; i < 4; i++)
        #pragma unroll
        for (int j = 0; j < 4; j++)
            qs[(ty * 4 + i) * 64 + tx * 4 + j] = p[i][j];
    __syncthreads();

    float oc[4][4] = {};
    #pragma unroll 4
    for (int t = 0; t < 64; t++) {
        const float4 vv = *(const float4*)&vs[t * 64 + tx * 4];
        #pragma unroll
        for (int i = 0; i < 4; i++) {
            const float pp = qs[(ty * 4 + i) * 64 + t];
            oc[i][0] += pp * vv.x; oc[i][1] += pp * vv.y;
            oc[i][2] += pp * vv.z; oc[i][3] += pp * vv.w;
        }
    }
    #pragma unroll
    for (int i = 0; i < 4; i++) {
        const int s = ty * 4 + i;
        const size_t off = (size_t)(s * B_ + b) * D_ + h * DH_ + tx * 4;
        const __nv_bfloat16 h0 = __float2bfloat16(oc[i][0]), h1 = __float2bfloat16(oc[i][1]);
        const __nv_bfloat16 h2 = __float2bfloat16(oc[i][2]), h3 = __float2bfloat16(oc[i][3]);
        uint2 hb;
        hb.x = (uint32_t)__bfloat16_as_ushort(h0) | ((uint32_t)__bfloat16_as_ushort(h1) << 16);
        hb.y = (uint32_t)__bfloat16_as_ushort(h2) | ((uint32_t)__bfloat16_as_ushort(h3) << 16);
        *(uint2*)&ohi[off] = hb;
        *(uint32_t*)&o8h[off] = pack_e4m3_4(oc[i][0] * SAH, oc[i][1] * SAH,
                                            oc[i][2] * SAH, oc[i][3] * SAH);
        *(uint32_t*)&o8l[off] = pack_e4m3_4((oc[i][0] - __bfloat162float(h0)) * SAL,
                                            (oc[i][1] - __bfloat162float(h1)) * SAL,
                                            (oc[i][2] - __bfloat162float(h2)) * SAL,
                                            (oc[i][3] - __bfloat162float(h3)) * SAL);
    }
}

// ---------------- mean over S ----------------
__global__ void pool_kernel(const float* __restrict__ x, float* __restrict__ pooled) {
    const int idx = blockIdx.x * blockDim.x + threadIdx.x;
    float s = 0.0f;
    #pragma unroll
    for (int t = 0; t < S_; t++) s += x[(size_t)t * BD + idx];
    pooled[idx] = s * (1.0f / 64.0f);
}

// ---------------- hashing head ----------------
__global__ void hash_kernel(const float* __restrict__ pooled, const float* __restrict__ hw,
                            const float* __restrict__ hb, float* __restrict__ out) {
    const int b = blockIdx.x;
    const int t = threadIdx.x;
    __shared__ float row[512];
    __shared__ float part[128];
    *(float4*)&row[t * 4] = *(const float4*)&pooled[(size_t)b * D_ + t * 4];
    __syncthreads();
    const int k = t & 31;
    const int pi = t >> 5;
    const float* w = hw + (size_t)k * D_ + pi * 128;
    const float* r = row + pi * 128;
    float s = 0.0f;
    #pragma unroll 8
    for (int d = 0; d < 128; d++) s += r[d] * w[d];
    part[t] = s;
    __syncthreads();
    if (t < 32) {
        const float v = part[t] + part[t + 32] + part[t + 64] + part[t + 96] + hb[t];
        out[(size_t)b * KBITS + t] = tanhf(v);
    }
}

// ---------------- orchestration ----------------
extern "C" void kernel_launch(void* const* d_in, const int* in_sizes, int n_in,
                              void* d_out, int out_size) {
    const float* x_in  = (const float*)d_in[0];
    const float* ln1_g = (const float*)d_in[1];
    const float* ln1_b = (const float*)d_in[2];
    const float* qkv_w = (const float*)d_in[3];
    const float* qkv_b = (const float*)d_in[4];
    const float* out_w = (const float*)d_in[5];
    const float* out_b = (const float*)d_in[6];
    const float* ln2_g = (const float*)d_in[7];
    const float* ln2_b = (const float*)d_in[8];
    const float* w1    = (const float*)d_in[9];
    const float* b1    = (const float*)d_in[10];
    const float* w2    = (const float*)d_in[11];
    const float* b2    = (const float*)d_in[12];
    const float* hw    = (const float*)d_in[13];
    const float* hb    = (const float*)d_in[14];
    float* out = (float*)d_out;

    float *gx, *gqkv, *gpool;
    __nv_bfloat16 *ahi, *hhi, *whi;
    uint8_t *a8h, *a8l, *h8h, *h8l, *w8h, *w8l;
    cudaGetSymbolAddress((void**)&gx,    g_x);
    cudaGetSymbolAddress((void**)&gqkv,  g_qkv);
    cudaGetSymbolAddress((void**)&gpool, g_pool);
    cudaGetSymbolAddress((void**)&ahi,   g_ahi);
    cudaGetSymbolAddress((void**)&a8h,   g_a8h);
    cudaGetSymbolAddress((void**)&a8l,   g_a8l);
    cudaGetSymbolAddress((void**)&hhi,   g_hhi);
    cudaGetSymbolAddress((void**)&h8h,   g_h8h);
    cudaGetSymbolAddress((void**)&h8l,   g_h8l);
    cudaGetSymbolAddress((void**)&whi,   g_whi);
    cudaGetSymbolAddress((void**)&w8h,   g_w8h);
    cudaGetSymbolAddress((void**)&w8l,   g_w8l);

    cudaFuncSetAttribute(mma_gemm<0>, cudaFuncAttributeMaxDynamicSharedMemorySize, GEMM_SMEM);
    cudaFuncSetAttribute(mma_gemm<1>, cudaFuncAttributeMaxDynamicSharedMemorySize, GEMM_SMEM);
    cudaFuncSetAttribute(mma_gemm<2>, cudaFuncAttributeMaxDynamicSharedMemorySize, GEMM_SMEM);

    pe_add_kernel<<<(NT * D_) / 256, 256>>>(x_in, gx);

    for (int i = 0; i < NL_; i++) {
        // --- attention block ---
        ln_kernel<<<NT, 128>>>(gx, ahi, a8h, a8l, ln1_g + i * D_, ln1_b + i * D_);
        wconv_kernel<<<(3 * D_ * D_) / 1024, 256>>>(qkv_w + (size_t)i * 3 * D_ * D_,
                                                    whi, w8h, w8l);
        mma_gemm<0><<<dim3(12, 512), 256, GEMM_SMEM>>>(
            ahi, a8h, a8l, whi, w8h, w8l, qkv_b + (size_t)i * 3 * D_, nullptr,
            gqkv, nullptr, nullptr, nullptr, 3 * D_, D_);
        attn_kernel<<<dim3(B_, H_), 256>>>(gqkv, ahi, a8h, a8l);
        wconv_kernel<<<(D_ * D_) / 1024, 256>>>(out_w + (size_t)i * D_ * D_, whi, w8h, w8l);
        mma_gemm<1><<<dim3(4, 512), 256, GEMM_SMEM>>>(
            ahi, a8h, a8l, whi, w8h, w8l, out_b + (size_t)i * D_, gx,
            gx, nullptr, nullptr, nullptr, D_, D_);
        // --- MLP block ---
        ln_kernel<<<NT, 128>>>(gx, ahi, a8h, a8l, ln2_g + i * D_, ln2_b + i * D_);
        wconv_kernel<<<(DFF_ * D_) / 1024, 256>>>(w1 + (size_t)i * DFF_ * D_, whi, w8h, w8l);
        mma_gemm<2><<<dim3(16, 512), 256, GEMM_SMEM>>>(
            ahi, a8h, a8l, whi, w8h, w8l, b1 + (size_t)i * DFF_, nullptr,
            nullptr, hhi, h8h, h8l, DFF_, D_);
        wconv_kernel<<<(D_ * DFF_) / 1024, 256>>>(w2 + (size_t)i * D_ * DFF_, whi, w8h, w8l);
        mma_gemm<1><<<dim3(4, 512), 256, GEMM_SMEM>>>(
            hhi, h8h, h8l, whi, w8h, w8l, b2 + (size_t)i * D_, gx,
            gx, nullptr, nullptr, nullptr, D_, DFF_);
    }

    pool_kernel<<<(B_ * D_) / 256, 256>>>(gx, gpool);
    hash_kernel<<<B_, 128>>>(gpool, hw, hb, out);
}

// round 11
// speedup vs baseline: 1.0072x; 1.0072x over previous
#include <cuda_runtime.h>
#include <cuda_bf16.h>
#include <cstdint>

// ---------------- problem constants ----------------
#define S_    64
#define B_    1024
#define D_    512
#define H_    8
#define DH_   64
#define NL_   4
#define DFF_  2048
#define NT    (S_ * B_)          // 65536 tokens
#define BD    (B_ * D_)          // 524288
#define KBITS 32

// ---------------- scratch (no cudaMalloc allowed) ----------------
__device__ float g_x[NT * D_];                                   // residual (fp32)
__device__ float g_qkv[NT * 3 * D_];                             // qkv (fp32)
__device__ float g_pool[B_ * D_];
__device__ __nv_bfloat16 g_ahi[NT * D_];                         // activation bf16 hi
__device__ uint8_t g_a8h[NT * D_];                               // activation e4m3(x*2^4)
__device__ uint8_t g_a8l[NT * D_];                               // activation e4m3(lo*2^13)
__device__ __nv_bfloat16 g_hhi[(size_t)NT * DFF_];               // hidden bf16 hi
__device__ uint8_t g_h8h[(size_t)NT * DFF_];
__device__ uint8_t g_h8l[(size_t)NT * DFF_];
__device__ __nv_bfloat16 g_whi[DFF_ * D_];                       // weight bf16(w)*2^24
__device__ uint8_t g_w8h[DFF_ * D_];                             // e4m3(w*2^11)
__device__ uint8_t g_w8l[DFF_ * D_];                             // e4m3(wlo*2^20)

// scales
#define DESCALE (1.0f / 16777216.0f)     // 2^-24
#define SAH 16.0f                        // 2^4
#define SAL 8192.0f                      // 2^13
#define SWH 2048.0f                      // 2^11
#define SWL 1048576.0f                   // 2^20
#define WBF_SCALE 16777216.0f            // 2^24 (exact on bf16)

// ---------------- helpers ----------------
__device__ __forceinline__ uint32_t smem_u32(const void* p) {
    uint32_t a;
    asm("{ .reg .u64 t; cvta.to.shared.u64 t, %1; cvt.u32.u64 %0, t; }" : "=r"(a) : "l"(p));
    return a;
}
__device__ __forceinline__ uint32_t packbf(float a, float b) {
    __nv_bfloat16 ha = __float2bfloat16(a), hb = __float2bfloat16(b);
    return (uint32_t)__bfloat16_as_ushort(ha) | ((uint32_t)__bfloat16_as_ushort(hb) << 16);
}
__device__ __forceinline__ uint16_t pack_e4m3_2(float f0, float f1) {
    uint16_t r;
    asm("cvt.rn.satfinite.e4m3x2.f32 %0, %1, %2;" : "=h"(r) : "f"(f1), "f"(f0));
    return r;   // byte0 = f0, byte1 = f1
}
__device__ __forceinline__ uint32_t pack_e4m3_4(float f0, float f1, float f2, float f3) {
    return (uint32_t)pack_e4m3_2(f0, f1) | ((uint32_t)pack_e4m3_2(f2, f3) << 16);
}

#define CP16(dst, src) \
    asm volatile("cp.async.ca.shared.global [%0], [%1], 16;" :: "r"(dst), "l"(src) : "memory")
#define CPCOMMIT() asm volatile("cp.async.commit_group;" ::: "memory")
#define CPWAIT(n)  asm volatile("cp.async.wait_group %0;" :: "n"(n) : "memory")

__device__ __forceinline__ void ldsm4(uint32_t* r, uint32_t addr) {
    asm volatile("ldmatrix.sync.aligned.m8n8.x4.shared.b16 {%0,%1,%2,%3}, [%4];"
                 : "=r"(r[0]), "=r"(r[1]), "=r"(r[2]), "=r"(r[3]) : "r"(addr));
}
__device__ __forceinline__ void mma16816(float* d, const uint32_t* a, const uint32_t* b) {
    asm volatile("mma.sync.aligned.m16n8k16.row.col.f32.bf16.bf16.f32 "
                 "{%0,%1,%2,%3}, {%4,%5,%6,%7}, {%8,%9}, {%0,%1,%2,%3};"
                 : "+f"(d[0]), "+f"(d[1]), "+f"(d[2]), "+f"(d[3])
                 : "r"(a[0]), "r"(a[1]), "r"(a[2]), "r"(a[3]), "r"(b[0]), "r"(b[1]));
}
__device__ __forceinline__ void mma16832f8(float* d, const uint32_t* a, const uint32_t* b) {
    asm volatile("mma.sync.aligned.m16n8k32.row.col.f32.e4m3.e4m3.f32 "
                 "{%0,%1,%2,%3}, {%4,%5,%6,%7}, {%8,%9}, {%0,%1,%2,%3};"
                 : "+f"(d[0]), "+f"(d[1]), "+f"(d[2]), "+f"(d[3])
                 : "r"(a[0]), "r"(a[1]), "r"(a[2]), "r"(a[3]), "r"(b[0]), "r"(b[1]));
}

__device__ __forceinline__ float qgelu(float t) { return t / (1.0f + __expf(-1.702f * t)); }

// smem stage (64KB): Abf16(16K) Wbf16(16K) A8packed(16K) W8packed(16K); 2 stages = 128KB
#define OFF_WBF  16384
#define OFF_A8   32768
#define OFF_W8   49152
#define STG_SZ   65536
#define GEMM_SMEM (2 * STG_SZ)

// ---------------- MMA GEMM: C[n,m] = epi(sum_k A[n,k]*W[m,k] + bias[m]) ----------------
// CTA tile: 128 tokens x 128 outputs, KC=64, 8 warps (warp tile 64 tok x 32 out).
// Pass 1 bf16 (W pre-scaled 2^24); passes 2+3 fp8 e4m3 k32 through a REUSED fragment
// pool (peak live frags 24, not 96) — same math as R10, no spills.
// EPI: 0 = f32 +bias ; 1 = f32 +bias+res ; 2 = QuickGELU -> (bf16 hi, fp8 hi, fp8 lo)
template <int EPI>
__global__ __launch_bounds__(256, 1) void mma_gemm(
    const __nv_bfloat16* __restrict__ Ahi, const uint8_t* __restrict__ A8h,
    const uint8_t* __restrict__ A8l,
    const __nv_bfloat16* __restrict__ Whi, const uint8_t* __restrict__ W8h,
    const uint8_t* __restrict__ W8l,
    const float* __restrict__ bias, const float* __restrict__ res,
    float* __restrict__ C, __nv_bfloat16* __restrict__ Chi,
    uint8_t* __restrict__ C8h, uint8_t* __restrict__ C8l,
    int M, int K)
{
    extern __shared__ __align__(128) char smem[];
    const uint32_t sb = smem_u32(smem);
    const int tid = threadIdx.x;
    const int lane = tid & 31;
    const int wid = tid >> 5;
    const int m0 = blockIdx.x * 128;
    const int n0 = blockIdx.y * 128;
    const int wm = (wid & 1) * 64;
    const int wn = (wid >> 1) * 32;
    const int NCH = K >> 6;
    const int lcc = tid & 7;

    float acc[4][4][4];
    #pragma unroll
    for (int a = 0; a < 4; a++)
        #pragma unroll
        for (int b = 0; b < 4; b++)
            #pragma unroll
            for (int c = 0; c < 4; c++) acc[a][b][c] = 0.0f;

    // ---- stage loader ----
    auto load_stage = [&](int c, int s) {
        const uint32_t stb = sb + s * STG_SZ;
        #pragma unroll
        for (int j = 0; j < 4; j++) {
            const int r = (j * 256 + tid) >> 3;
            const uint32_t dst = (uint32_t)(r * 128 + ((lcc ^ (r & 7)) << 4));
            const size_t arow = (size_t)(n0 + r) * K + c * 64;
            const size_t wrow = (size_t)(m0 + r) * K + c * 64;
            CP16(stb + dst,           Ahi + arow + lcc * 8);
            CP16(stb + OFF_WBF + dst, Whi + wrow + lcc * 8);
            // fp8 packed tiles: chunks 0-3 = hi (16 fp8 each), 4-7 = lo
            const uint8_t* a8src = (lcc < 4) ? (A8h + arow + lcc * 16)
                                             : (A8l + arow + (lcc - 4) * 16);
            const uint8_t* w8src = (lcc < 4) ? (W8h + wrow + lcc * 16)
                                             : (W8l + wrow + (lcc - 4) * 16);
            CP16(stb + OFF_A8 + dst, a8src);
            CP16(stb + OFF_W8 + dst, w8src);
        }
        CPCOMMIT();
    };

    load_stage(0, 0);

    const int g  = lane >> 3;
    const int lr = lane & 7;

    for (int c = 0; c < NCH; c++) {
        if (c + 1 < NCH) { load_stage(c + 1, (c + 1) & 1); CPWAIT(1); }
        else             { CPWAIT(0); }
        __syncthreads();

        const uint32_t stb = sb + (c & 1) * STG_SZ;

        // ---- bf16 main pass: 4 x k16 ----
        #pragma unroll
        for (int ks = 0; ks < 4; ks++) {
            uint32_t af[4][4], bf[2][4];
            #pragma unroll
            for (int mi = 0; mi < 4; mi++) {
                const int row = wm + mi * 16 + ((g & 1) << 3) + lr;
                const int ch = ks * 2 + (g >> 1);
                ldsm4(af[mi], stb + row * 128 + ((ch ^ (row & 7)) << 4));
            }
            #pragma unroll
            for (int np = 0; np < 2; np++) {
                const int row = wn + np * 16 + ((g >> 1) << 3) + lr;
                const int ch = ks * 2 + (g & 1);
                ldsm4(bf[np], stb + OFF_WBF + row * 128 + ((ch ^ (row & 7)) << 4));
            }
            #pragma unroll
            for (int mi = 0; mi < 4; mi++)
                #pragma unroll
                for (int nt = 0; nt < 4; nt++)
                    mma16816(acc[mi][nt], af[mi], &bf[nt >> 1][(nt & 1) * 2]);
        }

        // ---- fp8 correction passes: 2 x k32, reused fragment pool ----
        #pragma unroll
        for (int s = 0; s < 2; s++) {
            uint32_t a8[4][4], w8[2][4];
            // pass 2: Alo(fp8, chunks +4) * Whi(fp8, chunks +0) -> 2^13 * 2^11 = 2^24
            #pragma unroll
            for (int mi = 0; mi < 4; mi++) {
                const int row = wm + mi * 16 + ((g & 1) << 3) + lr;
                const int ch = s * 2 + (g >> 1);
                ldsm4(a8[mi], stb + OFF_A8 + row * 128 + (((ch + 4) ^ (row & 7)) << 4));
            }
            #pragma unroll
            for (int np = 0; np < 2; np++) {
                const int row = wn + np * 16 + ((g >> 1) << 3) + lr;
                const int ch = s * 2 + (g & 1);
                ldsm4(w8[np], stb + OFF_W8 + row * 128 + ((ch ^ (row & 7)) << 4));
            }
            #pragma unroll
            for (int mi = 0; mi < 4; mi++)
                #pragma unroll
                for (int nt = 0; nt < 4; nt++)
                    mma16832f8(acc[mi][nt], a8[mi], &w8[nt >> 1][(nt & 1) * 2]);
            // pass 3: Ahi(fp8, chunks +0) * Wlo(fp8, chunks +4) -> 2^4 * 2^20 = 2^24
            #pragma unroll
            for (int mi = 0; mi < 4; mi++) {
                const int row = wm + mi * 16 + ((g & 1) << 3) + lr;
                const int ch = s * 2 + (g >> 1);
                ldsm4(a8[mi], stb + OFF_A8 + row * 128 + ((ch ^ (row & 7)) << 4));
            }
            #pragma unroll
            for (int np = 0; np < 2; np++) {
                const int row = wn + np * 16 + ((g >> 1) << 3) + lr;
                const int ch = s * 2 + (g & 1);
                ldsm4(w8[np], stb + OFF_W8 + row * 128 + (((ch + 4) ^ (row & 7)) << 4));
            }
            #pragma unroll
            for (int mi = 0; mi < 4; mi++)
                #pragma unroll
                for (int nt = 0; nt < 4; nt++)
                    mma16832f8(acc[mi][nt], a8[mi], &w8[nt >> 1][(nt & 1) * 2]);
        }
        __syncthreads();
    }

    // ---- epilogue (descale 2^-24) ----
    const int r4 = lane >> 2;
    const int c2 = (lane & 3) * 2;
    #pragma unroll
    for (int mi = 0; mi < 4; mi++) {
        #pragma unroll
        for (int nt = 0; nt < 4; nt++) {
            const int row = n0 + wm + mi * 16 + r4;
            const int col = m0 + wn + nt * 8 + c2;
            const float b0 = bias[col], b1 = bias[col + 1];
            float v0 = acc[mi][nt][0] * DESCALE + b0, v1 = acc[mi][nt][1] * DESCALE + b1;
            float v2 = acc[mi][nt][2] * DESCALE + b0, v3 = acc[mi][nt][3] * DESCALE + b1;
            const size_t o0 = (size_t)row * M + col;
            const size_t o1 = (size_t)(row + 8) * M + col;
            if (EPI == 1) {
                const float2 r0 = *(const float2*)&res[o0];
                const float2 r1 = *(const float2*)&res[o1];
                v0 += r0.x; v1 += r0.y; v2 += r1.x; v3 += r1.y;
            }
            if (EPI == 2) {
                v0 = qgelu(v0); v1 = qgelu(v1); v2 = qgelu(v2); v3 = qgelu(v3);
                const __nv_bfloat16 h0 = __float2bfloat16(v0), h1 = __float2bfloat16(v1);
                const __nv_bfloat16 h2 = __float2bfloat16(v2), h3 = __float2bfloat16(v3);
                *(uint32_t*)&Chi[o0] = (uint32_t)__bfloat16_as_ushort(h0)
                                     | ((uint32_t)__bfloat16_as_ushort(h1) << 16);
                *(uint32_t*)&Chi[o1] = (uint32_t)__bfloat16_as_ushort(h2)
                                     | ((uint32_t)__bfloat16_as_ushort(h3) << 16);
                *(uint16_t*)&C8h[o0] = pack_e4m3_2(v0 * SAH, v1 * SAH);
                *(uint16_t*)&C8h[o1] = pack_e4m3_2(v2 * SAH, v3 * SAH);
                *(uint16_t*)&C8l[o0] = pack_e4m3_2((v0 - __bfloat162float(h0)) * SAL,
                                                   (v1 - __bfloat162float(h1)) * SAL);
                *(uint16_t*)&C8l[o1] = pack_e4m3_2((v2 - __bfloat162float(h2)) * SAL,
                                                   (v3 - __bfloat162float(h3)) * SAL);
            } else {
                *(float2*)&C[o0] = make_float2(v0, v1);
                *(float2*)&C[o1] = make_float2(v2, v3);
            }
        }
    }
}

// ---------------- weight convert: fp32 -> (bf16*2^24, fp8 hi, fp8 lo) ----------------
__global__ void wconv_kernel(const float* __restrict__ w,
                             __nv_bfloat16* __restrict__ whi,
                             uint8_t* __restrict__ w8h, uint8_t* __restrict__ w8l) {
    const int i = blockIdx.x * blockDim.x + threadIdx.x;
    const float4 v = *(const float4*)&w[i * 4];
    const __nv_bfloat16 h0 = __float2bfloat16(v.x), h1 = __float2bfloat16(v.y);
    const __nv_bfloat16 h2 = __float2bfloat16(v.z), h3 = __float2bfloat16(v.w);
    uint2 hb;
    hb.x = packbf(__bfloat162float(h0) * WBF_SCALE, __bfloat162float(h1) * WBF_SCALE);
    hb.y = packbf(__bfloat162float(h2) * WBF_SCALE, __bfloat162float(h3) * WBF_SCALE);
    *(uint2*)&whi[i * 4] = hb;
    *(uint32_t*)&w8h[i * 4] = pack_e4m3_4(v.x * SWH, v.y * SWH, v.z * SWH, v.w * SWH);
    *(uint32_t*)&w8l[i * 4] = pack_e4m3_4((v.x - __bfloat162float(h0)) * SWL,
                                          (v.y - __bfloat162float(h1)) * SWL,
                                          (v.z - __bfloat162float(h2)) * SWL,
                                          (v.w - __bfloat162float(h3)) * SWL);
}

// ---------------- positional encoding add ----------------
__global__ void pe_add_kernel(const float* __restrict__ xin, float* __restrict__ xout) {
    int idx = blockIdx.x * blockDim.x + threadIdx.x;
    int d = idx & (D_ - 1);
    int s = idx >> 19;
    int j2 = d & ~1;
    float ang = (float)s * expf((float)j2 * (-9.210340371976184f / 512.0f));
    float pe = ((d & 1) ? cosf(ang) : sinf(ang)) * 0.04419417382415922f;
    xout[idx] = xin[idx] + pe;
}

// ---------------- layernorm -> (bf16 hi, fp8 hi, fp8 lo) ----------------
__global__ void ln_kernel(const float* __restrict__ x,
                          __nv_bfloat16* __restrict__ yhi,
                          uint8_t* __restrict__ y8h, uint8_t* __restrict__ y8l,
                          const float* __restrict__ g, const float* __restrict__ b) {
    const int row = blockIdx.x;
    const int t = threadIdx.x;
    const size_t base = (size_t)row * D_ + t * 4;
    const float4 v = *(const float4*)&x[base];
    float s = v.x + v.y + v.z + v.w;
    float q = v.x * v.x + v.y * v.y + v.z * v.z + v.w * v.w;
    #pragma unroll
    for (int m = 16; m > 0; m >>= 1) {
        s += __shfl_xor_sync(0xffffffffu, s, m);
        q += __shfl_xor_sync(0xffffffffu, q, m);
    }
    __shared__ float ss[4], qq[4];
    if ((t & 31) == 0) { ss[t >> 5] = s; qq[t >> 5] = q; }
    __syncthreads();
    s = ss[0] + ss[1] + ss[2] + ss[3];
    q = qq[0] + qq[1] + qq[2] + qq[3];
    const float mean = s * (1.0f / 512.0f);
    const float var  = q * (1.0f / 512.0f) - mean * mean;
    const float rstd = rsqrtf(var + 1e-5f);
    const float4 gg = *(const float4*)&g[t * 4];
    const float4 bb = *(const float4*)&b[t * 4];
    const float o0 = (v.x - mean) * rstd * gg.x + bb.x;
    const float o1 = (v.y - mean) * rstd * gg.y + bb.y;
    const float o2 = (v.z - mean) * rstd * gg.z + bb.z;
    const float o3 = (v.w - mean) * rstd * gg.w + bb.w;
    const __nv_bfloat16 h0 = __float2bfloat16(o0), h1 = __float2bfloat16(o1);
    const __nv_bfloat16 h2 = __float2bfloat16(o2), h3 = __float2bfloat16(o3);
    uint2 hb;
    hb.x = (uint32_t)__bfloat16_as_ushort(h0) | ((uint32_t)__bfloat16_as_ushort(h1) << 16);
    hb.y = (uint32_t)__bfloat16_as_ushort(h2) | ((uint32_t)__bfloat16_as_ushort(h3) << 16);
    *(uint2*)&yhi[base] = hb;
    *(uint32_t*)&y8h[base] = pack_e4m3_4(o0 * SAH, o1 * SAH, o2 * SAH, o3 * SAH);
    *(uint32_t*)&y8l[base] = pack_e4m3_4((o0 - __bfloat162float(h0)) * SAL,
                                         (o1 - __bfloat162float(h1)) * SAL,
                                         (o2 - __bfloat162float(h2)) * SAL,
                                         (o3 - __bfloat162float(h3)) * SAL);
}

// ---------------- attention: one CTA per (batch, head) ----------------
__global__ __launch_bounds__(256) void attn_kernel(const float* __restrict__ qkv,
                                                   __nv_bfloat16* __restrict__ ohi,
                                                   uint8_t* __restrict__ o8h,
                                                   uint8_t* __restrict__ o8l) {
    __shared__ __align__(16) float qs[64 * 64];
    __shared__ __align__(16) float kst[64 * 64];
    __shared__ __align__(16) float vs[64 * 64];

    const int b = blockIdx.x;
    const int h = blockIdx.y;
    const int tid = threadIdx.x;
    const float* base = qkv + (size_t)b * (3 * D_) + h * DH_;

    #pragma unroll
    for (int it = 0; it < 4; it++) {
        const int idx = tid + it * 256;
        const int s = idx >> 4;
        const int f = idx & 15;
        const size_t g = (size_t)s * (B_ * 3 * D_) + f * 4;
        const float4 qv = *(const float4*)(base + g);
        const float4 kv = *(const float4*)(base + 512 + g);
        const float4 vv = *(const float4*)(base + 1024 + g);
        *(float4*)&qs[s * 64 + f * 4] = qv;
        kst[(f * 4 + 0) * 64 + s] = kv.x;
        kst[(f * 4 + 1) * 64 + s] = kv.y;
        kst[(f * 4 + 2) * 64 + s] = kv.z;
        kst[(f * 4 + 3) * 64 + s] = kv.w;
        *(float4*)&vs[s * 64 + f * 4] = vv;
    }
    __syncthreads();

    const int tx = tid & 15;
    const int ty = tid >> 4;

    float sc[4][4] = {};
    for (int d0 = 0; d0 < 64; d0 += 4) {
        const float4 k0 = *(const float4*)&kst[(d0 + 0) * 64 + tx * 4];
        const float4 k1 = *(const float4*)&kst[(d0 + 1) * 64 + tx * 4];
        const float4 k2 = *(const float4*)&kst[(d0 + 2) * 64 + tx * 4];
        const float4 k3 = *(const float4*)&kst[(d0 + 3) * 64 + tx * 4];
        #pragma unroll
        for (int i = 0; i < 4; i++) {
            const float4 q = *(const float4*)&qs[(ty * 4 + i) * 64 + d0];
            sc[i][0] += q.x * k0.x + q.y * k1.x + q.z * k2.x + q.w * k3.x;
            sc[i][1] += q.x * k0.y + q.y * k1.y + q.z * k2.y + q.w * k3.y;
            sc[i][2] += q.x * k0.z + q.y * k1.z + q.z * k2.z + q.w * k3.z;
            sc[i][3] += q.x * k0.w + q.y * k1.w + q.z * k2.w + q.w * k3.w;
        }
    }

    float p[4][4];
    #pragma unroll
    for (int i = 0; i < 4; i++) {
        #pragma unroll
        for (int j = 0; j < 4; j++) sc[i][j] *= 0.125f;
        float m = fmaxf(fmaxf(sc[i][0], sc[i][1]), fmaxf(sc[i][2], sc[i][3]));
        #pragma unroll
        for (int msk = 1; msk < 16; msk <<= 1) m = fmaxf(m, __shfl_xor_sync(0xffffffffu, m, msk));
        float s = 0.0f;
        #pragma unroll
        for (int j = 0; j < 4; j++) { p[i][j] = __expf(sc[i][j] - m); s += p[i][j]; }
        #pragma unroll
        for (int msk = 1; msk < 16; msk <<= 1) s += __shfl_xor_sync(0xffffffffu, s, msk);
        const float inv = 1.0f / s;
        #pragma unroll
        for (int j = 0; j < 4; j++) p[i][j] *= inv;
    }

    __syncthreads();
    #pragma unroll
    for (int i = 0; i < 4; i++)
        #pragma unroll
        for (int j = 0; j < 4; j++)
            qs[(ty * 4 + i) * 64 + tx * 4 + j] = p[i][j];
    __syncthreads();

    float oc[4][4] = {};
    #pragma unroll 4
    for (int t = 0; t < 64; t++) {
        const float4 vv = *(const float4*)&vs[t * 64 + tx * 4];
        #pragma unroll
        for (int i = 0; i < 4; i++) {
            const float pp = qs[(ty * 4 + i) * 64 + t];
            oc[i][0] += pp * vv.x; oc[i][1] += pp * vv.y;
            oc[i][2] += pp * vv.z; oc[i][3] += pp * vv.w;
        }
    }
    #pragma unroll
    for (int i = 0; i < 4; i++) {
        const int s = ty * 4 + i;
        const size_t off = (size_t)(s * B_ + b) * D_ + h * DH_ + tx * 4;
        const __nv_bfloat16 h0 = __float2bfloat16(oc[i][0]), h1 = __float2bfloat16(oc[i][1]);
        const __nv_bfloat16 h2 = __float2bfloat16(oc[i][2]), h3 = __float2bfloat16(oc[i][3]);
        uint2 hb;
        hb.x = (uint32_t)__bfloat16_as_ushort(h0) | ((uint32_t)__bfloat16_as_ushort(h1) << 16);
        hb.y = (uint32_t)__bfloat16_as_ushort(h2) | ((uint32_t)__bfloat16_as_ushort(h3) << 16);
        *(uint2*)&ohi[off] = hb;
        *(uint32_t*)&o8h[off] = pack_e4m3_4(oc[i][0] * SAH, oc[i][1] * SAH,
                                            oc[i][2] * SAH, oc[i][3] * SAH);
        *(uint32_t*)&o8l[off] = pack_e4m3_4((oc[i][0] - __bfloat162float(h0)) * SAL,
                                            (oc[i][1] - __bfloat162float(h1)) * SAL,
                                            (oc[i][2] - __bfloat162float(h2)) * SAL,
                                            (oc[i][3] - __bfloat162float(h3)) * SAL);
    }
}

// ---------------- mean over S ----------------
__global__ void pool_kernel(const float* __restrict__ x, float* __restrict__ pooled) {
    const int idx = blockIdx.x * blockDim.x + threadIdx.x;
    float s = 0.0f;
    #pragma unroll
    for (int t = 0; t < S_; t++) s += x[(size_t)t * BD + idx];
    pooled[idx] = s * (1.0f / 64.0f);
}

// ---------------- hashing head ----------------
__global__ void hash_kernel(const float* __restrict__ pooled, const float* __restrict__ hw,
                            const float* __restrict__ hb, float* __restrict__ out) {
    const int b = blockIdx.x;
    const int t = threadIdx.x;
    __shared__ float row[512];
    __shared__ float part[128];
    *(float4*)&row[t * 4] = *(const float4*)&pooled[(size_t)b * D_ + t * 4];
    __syncthreads();
    const int k = t & 31;
    const int pi = t >> 5;
    const float* w = hw + (size_t)k * D_ + pi * 128;
    const float* r = row + pi * 128;
    float s = 0.0f;
    #pragma unroll 8
    for (int d = 0; d < 128; d++) s += r[d] * w[d];
    part[t] = s;
    __syncthreads();
    if (t < 32) {
        const float v = part[t] + part[t + 32] + part[t + 64] + part[t + 96] + hb[t];
        out[(size_t)b * KBITS + t] = tanhf(v);
    }
}

// ---------------- orchestration ----------------
extern "C" void kernel_launch(void* const* d_in, const int* in_sizes, int n_in,
                              void* d_out, int out_size) {
    const float* x_in  = (const float*)d_in[0];
    const float* ln1_g = (const float*)d_in[1];
    const float* ln1_b = (const float*)d_in[2];
    const float* qkv_w = (const float*)d_in[3];
    const float* qkv_b = (const float*)d_in[4];
    const float* out_w = (const float*)d_in[5];
    const float* out_b = (const float*)d_in[6];
    const float* ln2_g = (const float*)d_in[7];
    const float* ln2_b = (const float*)d_in[8];
    const float* w1    = (const float*)d_in[9];
    const float* b1    = (const float*)d_in[10];
    const float* w2    = (const float*)d_in[11];
    const float* b2    = (const float*)d_in[12];
    const float* hw    = (const float*)d_in[13];
    const float* hb    = (const float*)d_in[14];
    float* out = (float*)d_out;

    float *gx, *gqkv, *gpool;
    __nv_bfloat16 *ahi, *hhi, *whi;
    uint8_t *a8h, *a8l, *h8h, *h8l, *w8h, *w8l;
    cudaGetSymbolAddress((void**)&gx,    g_x);
    cudaGetSymbolAddress((void**)&gqkv,  g_qkv);
    cudaGetSymbolAddress((void**)&gpool, g_pool);
    cudaGetSymbolAddress((void**)&ahi,   g_ahi);
    cudaGetSymbolAddress((void**)&a8h,   g_a8h);
    cudaGetSymbolAddress((void**)&a8l,   g_a8l);
    cudaGetSymbolAddress((void**)&hhi,   g_hhi);
    cudaGetSymbolAddress((void**)&h8h,   g_h8h);
    cudaGetSymbolAddress((void**)&h8l,   g_h8l);
    cudaGetSymbolAddress((void**)&whi,   g_whi);
    cudaGetSymbolAddress((void**)&w8h,   g_w8h);
    cudaGetSymbolAddress((void**)&w8l,   g_w8l);

    cudaFuncSetAttribute(mma_gemm<0>, cudaFuncAttributeMaxDynamicSharedMemorySize, GEMM_SMEM);
    cudaFuncSetAttribute(mma_gemm<1>, cudaFuncAttributeMaxDynamicSharedMemorySize, GEMM_SMEM);
    cudaFuncSetAttribute(mma_gemm<2>, cudaFuncAttributeMaxDynamicSharedMemorySize, GEMM_SMEM);

    pe_add_kernel<<<(NT * D_) / 256, 256>>>(x_in, gx);

    for (int i = 0; i < NL_; i++) {
        // --- attention block ---
        ln_kernel<<<NT, 128>>>(gx, ahi, a8h, a8l, ln1_g + i * D_, ln1_b + i * D_);
        wconv_kernel<<<(3 * D_ * D_) / 1024, 256>>>(qkv_w + (size_t)i * 3 * D_ * D_,
                                                    whi, w8h, w8l);
        mma_gemm<0><<<dim3(12, 512), 256, GEMM_SMEM>>>(
            ahi, a8h, a8l, whi, w8h, w8l, qkv_b + (size_t)i * 3 * D_, nullptr,
            gqkv, nullptr, nullptr, nullptr, 3 * D_, D_);
        attn_kernel<<<dim3(B_, H_), 256>>>(gqkv, ahi, a8h, a8l);
        wconv_kernel<<<(D_ * D_) / 1024, 256>>>(out_w + (size_t)i * D_ * D_, whi, w8h, w8l);
        mma_gemm<1><<<dim3(4, 512), 256, GEMM_SMEM>>>(
            ahi, a8h, a8l, whi, w8h, w8l, out_b + (size_t)i * D_, gx,
            gx, nullptr, nullptr, nullptr, D_, D_);
        // --- MLP block ---
        ln_kernel<<<NT, 128>>>(gx, ahi, a8h, a8l, ln2_g + i * D_, ln2_b + i * D_);
        wconv_kernel<<<(DFF_ * D_) / 1024, 256>>>(w1 + (size_t)i * DFF_ * D_, whi, w8h, w8l);
        mma_gemm<2><<<dim3(16, 512), 256, GEMM_SMEM>>>(
            ahi, a8h, a8l, whi, w8h, w8l, b1 + (size_t)i * DFF_, nullptr,
            nullptr, hhi, h8h, h8l, DFF_, D_);
        wconv_kernel<<<(D_ * DFF_) / 1024, 256>>>(w2 + (size_t)i * D_ * DFF_, whi, w8h, w8l);
        mma_gemm<1><<<dim3(4, 512), 256, GEMM_SMEM>>>(
            hhi, h8h, h8l, whi, w8h, w8l, b2 + (size_t)i * D_, gx,
            gx, nullptr, nullptr, nullptr, D_, DFF_);
    }

    pool_kernel<<<(B_ * D_) / 256, 256>>>(gx, gpool);
    hash_kernel<<<B_, 128>>>(gpool, hw, hb, out);
}

// round 12
// speedup vs baseline: 1.0611x; 1.0535x over previous
#include <cuda_runtime.h>
#include <cuda_bf16.h>
#include <cstdint>

// ---------------- problem constants ----------------
#define S_    64
#define B_    1024
#define D_    512
#define H_    8
#define DH_   64
#define NL_   4
#define DFF_  2048
#define NT    (S_ * B_)          // 65536 tokens
#define BD    (B_ * D_)          // 524288
#define KBITS 32

// ---------------- scratch (no cudaMalloc allowed) ----------------
__device__ float g_x[NT * D_];                                   // residual (fp32)
__device__ float g_qkv[NT * 3 * D_];                             // qkv (fp32)
__device__ float g_pool[B_ * D_];
__device__ __nv_bfloat16 g_ahi[NT * D_];                         // activation bf16 hi
__device__ uint8_t g_a8h[NT * D_];                               // activation e4m3(x*2^4)
__device__ uint8_t g_a8l[NT * D_];                               // activation e4m3(lo*2^13)
__device__ __nv_bfloat16 g_hhi[(size_t)NT * DFF_];               // hidden bf16 hi
__device__ uint8_t g_h8h[(size_t)NT * DFF_];
__device__ uint8_t g_h8l[(size_t)NT * DFF_];
__device__ __nv_bfloat16 g_whi[DFF_ * D_];                       // weight bf16(w)*2^24
__device__ uint8_t g_w8h[DFF_ * D_];                             // e4m3(w*2^11)
__device__ uint8_t g_w8l[DFF_ * D_];                             // e4m3(wlo*2^20)

// scales
#define DESCALE (1.0f / 16777216.0f)     // 2^-24
#define SAH 16.0f                        // 2^4
#define SAL 8192.0f                      // 2^13
#define SWH 2048.0f                      // 2^11
#define SWL 1048576.0f                   // 2^20
#define WBF_SCALE 16777216.0f            // 2^24 (exact on bf16)

// ---------------- helpers ----------------
__device__ __forceinline__ uint32_t smem_u32(const void* p) {
    uint32_t a;
    asm("{ .reg .u64 t; cvta.to.shared.u64 t, %1; cvt.u32.u64 %0, t; }" : "=r"(a) : "l"(p));
    return a;
}
__device__ __forceinline__ uint32_t packbf(float a, float b) {
    __nv_bfloat16 ha = __float2bfloat16(a), hb = __float2bfloat16(b);
    return (uint32_t)__bfloat16_as_ushort(ha) | ((uint32_t)__bfloat16_as_ushort(hb) << 16);
}
__device__ __forceinline__ uint16_t pack_e4m3_2(float f0, float f1) {
    uint16_t r;
    asm("cvt.rn.satfinite.e4m3x2.f32 %0, %1, %2;" : "=h"(r) : "f"(f1), "f"(f0));
    return r;   // byte0 = f0, byte1 = f1
}
__device__ __forceinline__ uint32_t pack_e4m3_4(float f0, float f1, float f2, float f3) {
    return (uint32_t)pack_e4m3_2(f0, f1) | ((uint32_t)pack_e4m3_2(f2, f3) << 16);
}

#define CP16(dst, src) \
    asm volatile("cp.async.ca.shared.global [%0], [%1], 16;" :: "r"(dst), "l"(src) : "memory")
#define CPCOMMIT() asm volatile("cp.async.commit_group;" ::: "memory")
#define CPWAIT(n)  asm volatile("cp.async.wait_group %0;" :: "n"(n) : "memory")

__device__ __forceinline__ void ldsm4(uint32_t* r, uint32_t addr) {
    asm volatile("ldmatrix.sync.aligned.m8n8.x4.shared.b16 {%0,%1,%2,%3}, [%4];"
                 : "=r"(r[0]), "=r"(r[1]), "=r"(r[2]), "=r"(r[3]) : "r"(addr));
}
__device__ __forceinline__ void mma16816(float* d, const uint32_t* a, const uint32_t* b) {
    asm volatile("mma.sync.aligned.m16n8k16.row.col.f32.bf16.bf16.f32 "
                 "{%0,%1,%2,%3}, {%4,%5,%6,%7}, {%8,%9}, {%0,%1,%2,%3};"
                 : "+f"(d[0]), "+f"(d[1]), "+f"(d[2]), "+f"(d[3])
                 : "r"(a[0]), "r"(a[1]), "r"(a[2]), "r"(a[3]), "r"(b[0]), "r"(b[1]));
}
__device__ __forceinline__ void mma16832f8(float* d, const uint32_t* a, const uint32_t* b) {
    asm volatile("mma.sync.aligned.m16n8k32.row.col.f32.e4m3.e4m3.f32 "
                 "{%0,%1,%2,%3}, {%4,%5,%6,%7}, {%8,%9}, {%0,%1,%2,%3};"
                 : "+f"(d[0]), "+f"(d[1]), "+f"(d[2]), "+f"(d[3])
                 : "r"(a[0]), "r"(a[1]), "r"(a[2]), "r"(a[3]), "r"(b[0]), "r"(b[1]));
}

__device__ __forceinline__ float qgelu(float t) { return t / (1.0f + __expf(-1.702f * t)); }

// smem stage (48KB): Abf16(16K) Wbf16(8K) A8packed(16K) W8packed(8K); 2 stages = 96KB
#define OFF_WBF  16384
#define OFF_A8   24576
#define OFF_W8   40960
#define STG_SZ   49152
#define GEMM_SMEM (2 * STG_SZ)

// ---------------- MMA GEMM: C[n,m] = epi(sum_k A[n,k]*W[m,k] + bias[m]) ----------------
// CTA tile: 128 tokens x 64 outputs, KC=64, 8 warps (warp tile 32 tok x 32 out).
// acc = 32 floats -> even a fully-hoisted fp8 fragment set fits under 255 regs.
// Pass 1 bf16 (W pre-scaled 2^24); passes 2+3 fp8 e4m3 k32; single accumulator.
// EPI: 0 = f32 +bias ; 1 = f32 +bias+res ; 2 = QuickGELU -> (bf16 hi, fp8 hi, fp8 lo)
template <int EPI>
__global__ __launch_bounds__(256, 1) void mma_gemm(
    const __nv_bfloat16* __restrict__ Ahi, const uint8_t* __restrict__ A8h,
    const uint8_t* __restrict__ A8l,
    const __nv_bfloat16* __restrict__ Whi, const uint8_t* __restrict__ W8h,
    const uint8_t* __restrict__ W8l,
    const float* __restrict__ bias, const float* __restrict__ res,
    float* __restrict__ C, __nv_bfloat16* __restrict__ Chi,
    uint8_t* __restrict__ C8h, uint8_t* __restrict__ C8l,
    int M, int K)
{
    extern __shared__ __align__(128) char smem[];
    const uint32_t sb = smem_u32(smem);
    const int tid = threadIdx.x;
    const int lane = tid & 31;
    const int wid = tid >> 5;            // 0..7
    const int m0 = blockIdx.x * 64;
    const int n0 = blockIdx.y * 128;
    const int wm = (wid & 3) * 32;       // token offset (4 slots x 32)
    const int wn = (wid >> 2) * 32;      // output offset (2 slots x 32)
    const int NCH = K >> 6;
    const int lcc = tid & 7;

    float acc[2][4][4];
    #pragma unroll
    for (int a = 0; a < 2; a++)
        #pragma unroll
        for (int b = 0; b < 4; b++)
            #pragma unroll
            for (int c = 0; c < 4; c++) acc[a][b][c] = 0.0f;

    // ---- stage loader ----
    auto load_stage = [&](int c, int s) {
        const uint32_t stb = sb + s * STG_SZ;
        #pragma unroll
        for (int j = 0; j < 4; j++) {               // A rows 0..127
            const int r = (j * 256 + tid) >> 3;
            const uint32_t dst = (uint32_t)(r * 128 + ((lcc ^ (r & 7)) << 4));
            const size_t arow = (size_t)(n0 + r) * K + c * 64;
            CP16(stb + dst, Ahi + arow + lcc * 8);
            const uint8_t* a8src = (lcc < 4) ? (A8h + arow + lcc * 16)
                                             : (A8l + arow + (lcc - 4) * 16);
            CP16(stb + OFF_A8 + dst, a8src);
        }
        #pragma unroll
        for (int j = 0; j < 2; j++) {               // W rows 0..63
            const int r = (j * 256 + tid) >> 3;
            const uint32_t dst = (uint32_t)(r * 128 + ((lcc ^ (r & 7)) << 4));
            const size_t wrow = (size_t)(m0 + r) * K + c * 64;
            CP16(stb + OFF_WBF + dst, Whi + wrow + lcc * 8);
            const uint8_t* w8src = (lcc < 4) ? (W8h + wrow + lcc * 16)
                                             : (W8l + wrow + (lcc - 4) * 16);
            CP16(stb + OFF_W8 + dst, w8src);
        }
        CPCOMMIT();
    };

    load_stage(0, 0);

    const int g  = lane >> 3;
    const int lr = lane & 7;

    for (int c = 0; c < NCH; c++) {
        if (c + 1 < NCH) { load_stage(c + 1, (c + 1) & 1); CPWAIT(1); }
        else             { CPWAIT(0); }
        __syncthreads();

        const uint32_t stb = sb + (c & 1) * STG_SZ;

        // ---- bf16 main pass: 4 x k16 ----
        #pragma unroll
        for (int ks = 0; ks < 4; ks++) {
            uint32_t af[2][4], bf[2][4];
            #pragma unroll
            for (int mi = 0; mi < 2; mi++) {
                const int row = wm + mi * 16 + ((g & 1) << 3) + lr;
                const int ch = ks * 2 + (g >> 1);
                ldsm4(af[mi], stb + row * 128 + ((ch ^ (row & 7)) << 4));
            }
            #pragma unroll
            for (int np = 0; np < 2; np++) {
                const int row = wn + np * 16 + ((g >> 1) << 3) + lr;
                const int ch = ks * 2 + (g & 1);
                ldsm4(bf[np], stb + OFF_WBF + row * 128 + ((ch ^ (row & 7)) << 4));
            }
            #pragma unroll
            for (int mi = 0; mi < 2; mi++)
                #pragma unroll
                for (int nt = 0; nt < 4; nt++)
                    mma16816(acc[mi][nt], af[mi], &bf[nt >> 1][(nt & 1) * 2]);
        }

        // ---- fp8 correction passes: 2 x k32 ----
        #pragma unroll
        for (int s = 0; s < 2; s++) {
            // pass 2: Alo(fp8, chunks +4) * Whi(fp8, chunks +0) -> 2^13 * 2^11 = 2^24
            {
                uint32_t a8[2][4], w8[2][4];
                #pragma unroll
                for (int mi = 0; mi < 2; mi++) {
                    const int row = wm + mi * 16 + ((g & 1) << 3) + lr;
                    const int ch = s * 2 + (g >> 1);
                    ldsm4(a8[mi], stb + OFF_A8 + row * 128 + (((ch + 4) ^ (row & 7)) << 4));
                }
                #pragma unroll
                for (int np = 0; np < 2; np++) {
                    const int row = wn + np * 16 + ((g >> 1) << 3) + lr;
                    const int ch = s * 2 + (g & 1);
                    ldsm4(w8[np], stb + OFF_W8 + row * 128 + ((ch ^ (row & 7)) << 4));
                }
                #pragma unroll
                for (int mi = 0; mi < 2; mi++)
                    #pragma unroll
                    for (int nt = 0; nt < 4; nt++)
                        mma16832f8(acc[mi][nt], a8[mi], &w8[nt >> 1][(nt & 1) * 2]);
            }
            // pass 3: Ahi(fp8, chunks +0) * Wlo(fp8, chunks +4) -> 2^4 * 2^20 = 2^24
            {
                uint32_t a8[2][4], w8[2][4];
                #pragma unroll
                for (int mi = 0; mi < 2; mi++) {
                    const int row = wm + mi * 16 + ((g & 1) << 3) + lr;
                    const int ch = s * 2 + (g >> 1);
                    ldsm4(a8[mi], stb + OFF_A8 + row * 128 + ((ch ^ (row & 7)) << 4));
                }
                #pragma unroll
                for (int np = 0; np < 2; np++) {
                    const int row = wn + np * 16 + ((g >> 1) << 3) + lr;
                    const int ch = s * 2 + (g & 1);
                    ldsm4(w8[np], stb + OFF_W8 + row * 128 + (((ch + 4) ^ (row & 7)) << 4));
                }
                #pragma unroll
                for (int mi = 0; mi < 2; mi++)
                    #pragma unroll
                    for (int nt = 0; nt < 4; nt++)
                        mma16832f8(acc[mi][nt], a8[mi], &w8[nt >> 1][(nt & 1) * 2]);
            }
        }
        __syncthreads();
    }

    // ---- epilogue (descale 2^-24) ----
    const int r4 = lane >> 2;
    const int c2 = (lane & 3) * 2;
    #pragma unroll
    for (int mi = 0; mi < 2; mi++) {
        #pragma unroll
        for (int nt = 0; nt < 4; nt++) {
            const int row = n0 + wm + mi * 16 + r4;
            const int col = m0 + wn + nt * 8 + c2;
            const float b0 = bias[col], b1 = bias[col + 1];
            float v0 = acc[mi][nt][0] * DESCALE + b0, v1 = acc[mi][nt][1] * DESCALE + b1;
            float v2 = acc[mi][nt][2] * DESCALE + b0, v3 = acc[mi][nt][3] * DESCALE + b1;
            const size_t o0 = (size_t)row * M + col;
            const size_t o1 = (size_t)(row + 8) * M + col;
            if (EPI == 1) {
                const float2 r0 = *(const float2*)&res[o0];
                const float2 r1 = *(const float2*)&res[o1];
                v0 += r0.x; v1 += r0.y; v2 += r1.x; v3 += r1.y;
            }
            if (EPI == 2) {
                v0 = qgelu(v0); v1 = qgelu(v1); v2 = qgelu(v2); v3 = qgelu(v3);
                const __nv_bfloat16 h0 = __float2bfloat16(v0), h1 = __float2bfloat16(v1);
                const __nv_bfloat16 h2 = __float2bfloat16(v2), h3 = __float2bfloat16(v3);
                *(uint32_t*)&Chi[o0] = (uint32_t)__bfloat16_as_ushort(h0)
                                     | ((uint32_t)__bfloat16_as_ushort(h1) << 16);
                *(uint32_t*)&Chi[o1] = (uint32_t)__bfloat16_as_ushort(h2)
                                     | ((uint32_t)__bfloat16_as_ushort(h3) << 16);
                *(uint16_t*)&C8h[o0] = pack_e4m3_2(v0 * SAH, v1 * SAH);
                *(uint16_t*)&C8h[o1] = pack_e4m3_2(v2 * SAH, v3 * SAH);
                *(uint16_t*)&C8l[o0] = pack_e4m3_2((v0 - __bfloat162float(h0)) * SAL,
                                                   (v1 - __bfloat162float(h1)) * SAL);
                *(uint16_t*)&C8l[o1] = pack_e4m3_2((v2 - __bfloat162float(h2)) * SAL,
                                                   (v3 - __bfloat162float(h3)) * SAL);
            } else {
                *(float2*)&C[o0] = make_float2(v0, v1);
                *(float2*)&C[o1] = make_float2(v2, v3);
            }
        }
    }
}

// ---------------- weight convert: fp32 -> (bf16*2^24, fp8 hi, fp8 lo) ----------------
__global__ void wconv_kernel(const float* __restrict__ w,
                             __nv_bfloat16* __restrict__ whi,
                             uint8_t* __restrict__ w8h, uint8_t* __restrict__ w8l) {
    const int i = blockIdx.x * blockDim.x + threadIdx.x;
    const float4 v = *(const float4*)&w[i * 4];
    const __nv_bfloat16 h0 = __float2bfloat16(v.x), h1 = __float2bfloat16(v.y);
    const __nv_bfloat16 h2 = __float2bfloat16(v.z), h3 = __float2bfloat16(v.w);
    uint2 hb;
    hb.x = packbf(__bfloat162float(h0) * WBF_SCALE, __bfloat162float(h1) * WBF_SCALE);
    hb.y = packbf(__bfloat162float(h2) * WBF_SCALE, __bfloat162float(h3) * WBF_SCALE);
    *(uint2*)&whi[i * 4] = hb;
    *(uint32_t*)&w8h[i * 4] = pack_e4m3_4(v.x * SWH, v.y * SWH, v.z * SWH, v.w * SWH);
    *(uint32_t*)&w8l[i * 4] = pack_e4m3_4((v.x - __bfloat162float(h0)) * SWL,
                                          (v.y - __bfloat162float(h1)) * SWL,
                                          (v.z - __bfloat162float(h2)) * SWL,
                                          (v.w - __bfloat162float(h3)) * SWL);
}

// ---------------- positional encoding add ----------------
__global__ void pe_add_kernel(const float* __restrict__ xin, float* __restrict__ xout) {
    int idx = blockIdx.x * blockDim.x + threadIdx.x;
    int d = idx & (D_ - 1);
    int s = idx >> 19;
    int j2 = d & ~1;
    float ang = (float)s * expf((float)j2 * (-9.210340371976184f / 512.0f));
    float pe = ((d & 1) ? cosf(ang) : sinf(ang)) * 0.04419417382415922f;
    xout[idx] = xin[idx] + pe;
}

// ---------------- layernorm -> (bf16 hi, fp8 hi, fp8 lo) ----------------
__global__ void ln_kernel(const float* __restrict__ x,
                          __nv_bfloat16* __restrict__ yhi,
                          uint8_t* __restrict__ y8h, uint8_t* __restrict__ y8l,
                          const float* __restrict__ g, const float* __restrict__ b) {
    const int row = blockIdx.x;
    const int t = threadIdx.x;
    const size_t base = (size_t)row * D_ + t * 4;
    const float4 v = *(const float4*)&x[base];
    float s = v.x + v.y + v.z + v.w;
    float q = v.x * v.x + v.y * v.y + v.z * v.z + v.w * v.w;
    #pragma unroll
    for (int m = 16; m > 0; m >>= 1) {
        s += __shfl_xor_sync(0xffffffffu, s, m);
        q += __shfl_xor_sync(0xffffffffu, q, m);
    }
    __shared__ float ss[4], qq[4];
    if ((t & 31) == 0) { ss[t >> 5] = s; qq[t >> 5] = q; }
    __syncthreads();
    s = ss[0] + ss[1] + ss[2] + ss[3];
    q = qq[0] + qq[1] + qq[2] + qq[3];
    const float mean = s * (1.0f / 512.0f);
    const float var  = q * (1.0f / 512.0f) - mean * mean;
    const float rstd = rsqrtf(var + 1e-5f);
    const float4 gg = *(const float4*)&g[t * 4];
    const float4 bb = *(const float4*)&b[t * 4];
    const float o0 = (v.x - mean) * rstd * gg.x + bb.x;
    const float o1 = (v.y - mean) * rstd * gg.y + bb.y;
    const float o2 = (v.z - mean) * rstd * gg.z + bb.z;
    const float o3 = (v.w - mean) * rstd * gg.w + bb.w;
    const __nv_bfloat16 h0 = __float2bfloat16(o0), h1 = __float2bfloat16(o1);
    const __nv_bfloat16 h2 = __float2bfloat16(o2), h3 = __float2bfloat16(o3);
    uint2 hb;
    hb.x = (uint32_t)__bfloat16_as_ushort(h0) | ((uint32_t)__bfloat16_as_ushort(h1) << 16);
    hb.y = (uint32_t)__bfloat16_as_ushort(h2) | ((uint32_t)__bfloat16_as_ushort(h3) << 16);
    *(uint2*)&yhi[base] = hb;
    *(uint32_t*)&y8h[base] = pack_e4m3_4(o0 * SAH, o1 * SAH, o2 * SAH, o3 * SAH);
    *(uint32_t*)&y8l[base] = pack_e4m3_4((o0 - __bfloat162float(h0)) * SAL,
                                         (o1 - __bfloat162float(h1)) * SAL,
                                         (o2 - __bfloat162float(h2)) * SAL,
                                         (o3 - __bfloat162float(h3)) * SAL);
}

// ---------------- attention: one CTA per (batch, head) ----------------
__global__ __launch_bounds__(256) void attn_kernel(const float* __restrict__ qkv,
                                                   __nv_bfloat16* __restrict__ ohi,
                                                   uint8_t* __restrict__ o8h,
                                                   uint8_t* __restrict__ o8l) {
    __shared__ __align__(16) float qs[64 * 64];
    __shared__ __align__(16) float kst[64 * 64];
    __shared__ __align__(16) float vs[64 * 64];

    const int b = blockIdx.x;
    const int h = blockIdx.y;
    const int tid = threadIdx.x;
    const float* base = qkv + (size_t)b * (3 * D_) + h * DH_;

    #pragma unroll
    for (int it = 0; it < 4; it++) {
        const int idx = tid + it * 256;
        const int s = idx >> 4;
        const int f = idx & 15;
        const size_t g = (size_t)s * (B_ * 3 * D_) + f * 4;
        const float4 qv = *(const float4*)(base + g);
        const float4 kv = *(const float4*)(base + 512 + g);
        const float4 vv = *(const float4*)(base + 1024 + g);
        *(float4*)&qs[s * 64 + f * 4] = qv;
        kst[(f * 4 + 0) * 64 + s] = kv.x;
        kst[(f * 4 + 1) * 64 + s] = kv.y;
        kst[(f * 4 + 2) * 64 + s] = kv.z;
        kst[(f * 4 + 3) * 64 + s] = kv.w;
        *(float4*)&vs[s * 64 + f * 4] = vv;
    }
    __syncthreads();

    const int tx = tid & 15;
    const int ty = tid >> 4;

    float sc[4][4] = {};
    for (int d0 = 0; d0 < 64; d0 += 4) {
        const float4 k0 = *(const float4*)&kst[(d0 + 0) * 64 + tx * 4];
        const float4 k1 = *(const float4*)&kst[(d0 + 1) * 64 + tx * 4];
        const float4 k2 = *(const float4*)&kst[(d0 + 2) * 64 + tx * 4];
        const float4 k3 = *(const float4*)&kst[(d0 + 3) * 64 + tx * 4];
        #pragma unroll
        for (int i = 0; i < 4; i++) {
            const float4 q = *(const float4*)&qs[(ty * 4 + i) * 64 + d0];
            sc[i][0] += q.x * k0.x + q.y * k1.x + q.z * k2.x + q.w * k3.x;
            sc[i][1] += q.x * k0.y + q.y * k1.y + q.z * k2.y + q.w * k3.y;
            sc[i][2] += q.x * k0.z + q.y * k1.z + q.z * k2.z + q.w * k3.z;
            sc[i][3] += q.x * k0.w + q.y * k1.w + q.z * k2.w + q.w * k3.w;
        }
    }

    float p[4][4];
    #pragma unroll
    for (int i = 0; i < 4; i++) {
        #pragma unroll
        for (int j = 0; j < 4; j++) sc[i][j] *= 0.125f;
        float m = fmaxf(fmaxf(sc[i][0], sc[i][1]), fmaxf(sc[i][2], sc[i][3]));
        #pragma unroll
        for (int msk = 1; msk < 16; msk <<= 1) m = fmaxf(m, __shfl_xor_sync(0xffffffffu, m, msk));
        float s = 0.0f;
        #pragma unroll
        for (int j = 0; j < 4; j++) { p[i][j] = __expf(sc[i][j] - m); s += p[i][j]; }
        #pragma unroll
        for (int msk = 1; msk < 16; msk <<= 1) s += __shfl_xor_sync(0xffffffffu, s, msk);
        const float inv = 1.0f / s;
        #pragma unroll
        for (int j = 0; j < 4; j++) p[i][j] *= inv;
    }

    __syncthreads();
    #pragma unroll
    for (int i = 0; i < 4; i++)
        #pragma unroll
        for (int j = 0; j < 4; j++)
            qs[(ty * 4 + i) * 64 + tx * 4 + j] = p[i][j];
    __syncthreads();

    float oc[4][4] = {};
    #pragma unroll 4
    for (int t = 0; t < 64; t++) {
        const float4 vv = *(const float4*)&vs[t * 64 + tx * 4];
        #pragma unroll
        for (int i = 0; i < 4; i++) {
            const float pp = qs[(ty * 4 + i) * 64 + t];
            oc[i][0] += pp * vv.x; oc[i][1] += pp * vv.y;
            oc[i][2] += pp * vv.z; oc[i][3] += pp * vv.w;
        }
    }
    #pragma unroll
    for (int i = 0; i < 4; i++) {
        const int s = ty * 4 + i;
        const size_t off = (size_t)(s * B_ + b) * D_ + h * DH_ + tx * 4;
        const __nv_bfloat16 h0 = __float2bfloat16(oc[i][0]), h1 = __float2bfloat16(oc[i][1]);
        const __nv_bfloat16 h2 = __float2bfloat16(oc[i][2]), h3 = __float2bfloat16(oc[i][3]);
        uint2 hb;
        hb.x = (uint32_t)__bfloat16_as_ushort(h0) | ((uint32_t)__bfloat16_as_ushort(h1) << 16);
        hb.y = (uint32_t)__bfloat16_as_ushort(h2) | ((uint32_t)__bfloat16_as_ushort(h3) << 16);
        *(uint2*)&ohi[off] = hb;
        *(uint32_t*)&o8h[off] = pack_e4m3_4(oc[i][0] * SAH, oc[i][1] * SAH,
                                            oc[i][2] * SAH, oc[i][3] * SAH);
        *(uint32_t*)&o8l[off] = pack_e4m3_4((oc[i][0] - __bfloat162float(h0)) * SAL,
                                            (oc[i][1] - __bfloat162float(h1)) * SAL,
                                            (oc[i][2] - __bfloat162float(h2)) * SAL,
                                            (oc[i][3] - __bfloat162float(h3)) * SAL);
    }
}

// ---------------- mean over S ----------------
__global__ void pool_kernel(const float* __restrict__ x, float* __restrict__ pooled) {
    const int idx = blockIdx.x * blockDim.x + threadIdx.x;
    float s = 0.0f;
    #pragma unroll
    for (int t = 0; t < S_; t++) s += x[(size_t)t * BD + idx];
    pooled[idx] = s * (1.0f / 64.0f);
}

// ---------------- hashing head ----------------
__global__ void hash_kernel(const float* __restrict__ pooled, const float* __restrict__ hw,
                            const float* __restrict__ hb, float* __restrict__ out) {
    const int b = blockIdx.x;
    const int t = threadIdx.x;
    __shared__ float row[512];
    __shared__ float part[128];
    *(float4*)&row[t * 4] = *(const float4*)&pooled[(size_t)b * D_ + t * 4];
    __syncthreads();
    const int k = t & 31;
    const int pi = t >> 5;
    const float* w = hw + (size_t)k * D_ + pi * 128;
    const float* r = row + pi * 128;
    float s = 0.0f;
    #pragma unroll 8
    for (int d = 0; d < 128; d++) s += r[d] * w[d];
    part[t] = s;
    __syncthreads();
    if (t < 32) {
        const float v = part[t] + part[t + 32] + part[t + 64] + part[t + 96] + hb[t];
        out[(size_t)b * KBITS + t] = tanhf(v);
    }
}

// ---------------- orchestration ----------------
extern "C" void kernel_launch(void* const* d_in, const int* in_sizes, int n_in,
                              void* d_out, int out_size) {
    const float* x_in  = (const float*)d_in[0];
    const float* ln1_g = (const float*)d_in[1];
    const float* ln1_b = (const float*)d_in[2];
    const float* qkv_w = (const float*)d_in[3];
    const float* qkv_b = (const float*)d_in[4];
    const float* out_w = (const float*)d_in[5];
    const float* out_b = (const float*)d_in[6];
    const float* ln2_g = (const float*)d_in[7];
    const float* ln2_b = (const float*)d_in[8];
    const float* w1    = (const float*)d_in[9];
    const float* b1    = (const float*)d_in[10];
    const float* w2    = (const float*)d_in[11];
    const float* b2    = (const float*)d_in[12];
    const float* hw    = (const float*)d_in[13];
    const float* hb    = (const float*)d_in[14];
    float* out = (float*)d_out;

    float *gx, *gqkv, *gpool;
    __nv_bfloat16 *ahi, *hhi, *whi;
    uint8_t *a8h, *a8l, *h8h, *h8l, *w8h, *w8l;
    cudaGetSymbolAddress((void**)&gx,    g_x);
    cudaGetSymbolAddress((void**)&gqkv,  g_qkv);
    cudaGetSymbolAddress((void**)&gpool, g_pool);
    cudaGetSymbolAddress((void**)&ahi,   g_ahi);
    cudaGetSymbolAddress((void**)&a8h,   g_a8h);
    cudaGetSymbolAddress((void**)&a8l,   g_a8l);
    cudaGetSymbolAddress((void**)&hhi,   g_hhi);
    cudaGetSymbolAddress((void**)&h8h,   g_h8h);
    cudaGetSymbolAddress((void**)&h8l,   g_h8l);
    cudaGetSymbolAddress((void**)&whi,   g_whi);
    cudaGetSymbolAddress((void**)&w8h,   g_w8h);
    cudaGetSymbolAddress((void**)&w8l,   g_w8l);

    cudaFuncSetAttribute(mma_gemm<0>, cudaFuncAttributeMaxDynamicSharedMemorySize, GEMM_SMEM);
    cudaFuncSetAttribute(mma_gemm<1>, cudaFuncAttributeMaxDynamicSharedMemorySize, GEMM_SMEM);
    cudaFuncSetAttribute(mma_gemm<2>, cudaFuncAttributeMaxDynamicSharedMemorySize, GEMM_SMEM);

    pe_add_kernel<<<(NT * D_) / 256, 256>>>(x_in, gx);

    for (int i = 0; i < NL_; i++) {
        // --- attention block ---
        ln_kernel<<<NT, 128>>>(gx, ahi, a8h, a8l, ln1_g + i * D_, ln1_b + i * D_);
        wconv_kernel<<<(3 * D_ * D_) / 1024, 256>>>(qkv_w + (size_t)i * 3 * D_ * D_,
                                                    whi, w8h, w8l);
        mma_gemm<0><<<dim3(24, 512), 256, GEMM_SMEM>>>(
            ahi, a8h, a8l, whi, w8h, w8l, qkv_b + (size_t)i * 3 * D_, nullptr,
            gqkv, nullptr, nullptr, nullptr, 3 * D_, D_);
        attn_kernel<<<dim3(B_, H_), 256>>>(gqkv, ahi, a8h, a8l);
        wconv_kernel<<<(D_ * D_) / 1024, 256>>>(out_w + (size_t)i * D_ * D_, whi, w8h, w8l);
        mma_gemm<1><<<dim3(8, 512), 256, GEMM_SMEM>>>(
            ahi, a8h, a8l, whi, w8h, w8l, out_b + (size_t)i * D_, gx,
            gx, nullptr, nullptr, nullptr, D_, D_);
        // --- MLP block ---
        ln_kernel<<<NT, 128>>>(gx, ahi, a8h, a8l, ln2_g + i * D_, ln2_b + i * D_);
        wconv_kernel<<<(DFF_ * D_) / 1024, 256>>>(w1 + (size_t)i * DFF_ * D_, whi, w8h, w8l);
        mma_gemm<2><<<dim3(32, 512), 256, GEMM_SMEM>>>(
            ahi, a8h, a8l, whi, w8h, w8l, b1 + (size_t)i * DFF_, nullptr,
            nullptr, hhi, h8h, h8l, DFF_, D_);
        wconv_kernel<<<(D_ * DFF_) / 1024, 256>>>(w2 + (size_t)i * D_ * DFF_, whi, w8h, w8l);
        mma_gemm<1><<<dim3(8, 512), 256, GEMM_SMEM>>>(
            hhi, h8h, h8l, whi, w8h, w8l, b2 + (size_t)i * D_, gx,
            gx, nullptr, nullptr, nullptr, D_, DFF_);
    }

    pool_kernel<<<(B_ * D_) / 256, 256>>>(gx, gpool);
    hash_kernel<<<B_, 128>>>(gpool, hw, hb, out);
}